// round 7
// baseline (speedup 1.0000x reference)
#include <cuda_runtime.h>
#include <cuda_bf16.h>
#include <cstdint>

// Problem constants
#define BATCH 8
#define NQ 1024
#define NKV 1024
#define DIM 1024
#define NHEADS 16
#define HDIM 64
#define MROWS (BATCH * NQ)     // 8192
#define U32DIM (DIM / 2)       // 512 u32 per row
#define U4DIM (DIM / 8)        // 128 uint4 per row
#define U4ROW (U32DIM / 4)     // 128

// ---------------------------------------------------------------------------
// Scratch (device globals; allocation is not allowed)
// ---------------------------------------------------------------------------
__device__ unsigned g_xh[MROWS * U32DIM], g_xl[MROWS * U32DIM];
__device__ unsigned g_ch[MROWS * U32DIM], g_cl[MROWS * U32DIM];
__device__ unsigned g_Wqh[DIM * U32DIM], g_Wql[DIM * U32DIM];
__device__ unsigned g_Wkh[DIM * U32DIM], g_Wkl[DIM * U32DIM];
__device__ unsigned g_Wvh[DIM * U32DIM], g_Wvl[DIM * U32DIM];
__device__ unsigned g_Woh[DIM * U32DIM], g_Wol[DIM * U32DIM];
__device__ unsigned g_Qh[MROWS * U32DIM], g_Ql[MROWS * U32DIM];
__device__ unsigned g_Kh[MROWS * U32DIM], g_Kl[MROWS * U32DIM];
__device__ unsigned g_Vh[MROWS * U32DIM], g_Vl[MROWS * U32DIM];
__device__ unsigned g_Oh[MROWS * U32DIM], g_Ol[MROWS * U32DIM];

// ---------------------------------------------------------------------------
// helpers
// ---------------------------------------------------------------------------
__device__ __forceinline__ void split2(float x, float y, unsigned &hi, unsigned &lo) {
    __nv_bfloat162 h = __floats2bfloat162_rn(x, y);
    float hx = __bfloat162float(h.x);
    float hy = __bfloat162float(h.y);
    __nv_bfloat162 l = __floats2bfloat162_rn(x - hx, y - hy);
    hi = *reinterpret_cast<unsigned*>(&h);
    lo = *reinterpret_cast<unsigned*>(&l);
}

__device__ __forceinline__ void mma16816(float* c, const unsigned* a, unsigned b0, unsigned b1) {
    asm volatile(
        "mma.sync.aligned.m16n8k16.row.col.f32.bf16.bf16.f32 "
        "{%0,%1,%2,%3}, {%4,%5,%6,%7}, {%8,%9}, {%0,%1,%2,%3};\n"
        : "+f"(c[0]), "+f"(c[1]), "+f"(c[2]), "+f"(c[3])
        : "r"(a[0]), "r"(a[1]), "r"(a[2]), "r"(a[3]), "r"(b0), "r"(b1));
}

__device__ __forceinline__ float ex2(float x) {
    float r;
    asm("ex2.approx.f32 %0, %1;" : "=f"(r) : "f"(x));
    return r;
}

__device__ __forceinline__ uint32_t smem_u32(const void* p) {
    uint32_t a;
    asm("{ .reg .u64 t; cvta.to.shared.u64 t, %1; cvt.u32.u64 %0, t; }" : "=r"(a) : "l"(p));
    return a;
}

#define LDSM4(r0, r1, r2, r3, addr) \
    asm volatile("ldmatrix.sync.aligned.m8n8.x4.shared.b16 {%0,%1,%2,%3}, [%4];" \
                 : "=r"(r0), "=r"(r1), "=r"(r2), "=r"(r3) : "r"(addr))

#define LDSM4T(r0, r1, r2, r3, addr) \
    asm volatile("ldmatrix.sync.aligned.m8n8.x4.trans.shared.b16 {%0,%1,%2,%3}, [%4];" \
                 : "=r"(r0), "=r"(r1), "=r"(r2), "=r"(r3) : "r"(addr))

#define CPA16(dst, src) \
    asm volatile("cp.async.cg.shared.global [%0], [%1], 16;" :: "r"(dst), "l"(src))
#define CPCOMMIT() asm volatile("cp.async.commit_group;")
#define CPWAIT1()  asm volatile("cp.async.wait_group 1;")
#define CPWAIT0()  asm volatile("cp.async.wait_group 0;")

// ---------------------------------------------------------------------------
// one-shot conversions
// ---------------------------------------------------------------------------
__global__ __launch_bounds__(256) void split_kernel(
    const float* __restrict__ src, unsigned* __restrict__ hi,
    unsigned* __restrict__ lo, int n2)
{
    int i = blockIdx.x * 256 + threadIdx.x;
    if (i < n2) {
        float2 v = reinterpret_cast<const float2*>(src)[i];
        unsigned h, l;
        split2(v.x, v.y, h, l);
        hi[i] = h;
        lo[i] = l;
    }
}

// W[k][n] -> Wt[n][k] as bf16 hi/lo (u32 = k-pair)
__global__ __launch_bounds__(256) void tsplit_kernel(
    const float* __restrict__ W, unsigned* __restrict__ Th, unsigned* __restrict__ Tl)
{
    __shared__ float t[64][65];
    const int k0 = blockIdx.y * 64, n0 = blockIdx.x * 64;
#pragma unroll
    for (int i = 0; i < 16; i++) {
        int idx = threadIdx.x + i * 256;
        int k = idx >> 6, n = idx & 63;
        t[k][n] = W[(size_t)(k0 + k) * DIM + n0 + n];
    }
    __syncthreads();
#pragma unroll
    for (int i = 0; i < 8; i++) {
        int idx = threadIdx.x + i * 256;
        int n = idx >> 5, kp = idx & 31;
        unsigned h, l;
        split2(t[2 * kp][n], t[2 * kp + 1][n], h, l);
        size_t o = (size_t)(n0 + n) * U32DIM + k0 / 2 + kp;
        Th[o] = h;
        Tl[o] = l;
    }
}

// ---------------------------------------------------------------------------
// GEMM (pre-split bf16, 3-stage cp.async, ONE sync per chunk):
//   C[8192,1024] = A @ Wt^T + bias.  Block 128x128, k-chunk 32, 8 warps,
//   warp tile 32x64, 1 CTA/SM (120KB smem).  bf16x3 accumulate.
//   mode 0: Cf = fp32.  mode 1: split(val*scale) -> Ch/Cl.
// ---------------------------------------------------------------------------
#define GST 20        // row stride in u32 (80B, conflict-free for ldmatrix)
#define OAH 0
#define OAL 2560
#define OBH 5120
#define OBL 7680
#define GSTG 10240    // u32 per stage (40KB)
#define GSMEM_BYTES (3 * GSTG * 4)   // 122880

__global__ __launch_bounds__(256, 1) void gemm_bf16_kernel(
    const unsigned* __restrict__ Ahp, const unsigned* __restrict__ Alp,
    const unsigned* __restrict__ Bhp, const unsigned* __restrict__ Blp,
    const float* __restrict__ bias, float* __restrict__ Cf,
    unsigned* __restrict__ Ch, unsigned* __restrict__ Cl,
    float scale, int mode)
{
    extern __shared__ unsigned gsm[];
    const uint32_t sb = smem_u32(gsm);

    const int tid  = threadIdx.x;
    const int lane = tid & 31;
    const int warp = tid >> 5;
    const int grp  = lane >> 2;
    const int q4   = lane & 3;
    const int wm   = warp >> 1;   // 0..3 (32-row group)
    const int wn   = warp & 1;    // 0..1 (64-col group)
    const int m0 = blockIdx.y * 128;
    const int n0 = blockIdx.x * 128;

    const uint4* A4h = reinterpret_cast<const uint4*>(Ahp);
    const uint4* A4l = reinterpret_cast<const uint4*>(Alp);
    const uint4* B4h = reinterpret_cast<const uint4*>(Bhp);
    const uint4* B4l = reinterpret_cast<const uint4*>(Blp);

    float acc[2][4][2][4];   // [mi][tt][half][4]
#pragma unroll
    for (int a = 0; a < 2; a++)
#pragma unroll
        for (int b = 0; b < 4; b++)
#pragma unroll
            for (int c = 0; c < 2; c++)
#pragma unroll
                for (int d = 0; d < 4; d++) acc[a][b][c][d] = 0.f;

    const int crow = tid >> 2;          // 0..63
    const int cj   = tid & 3;

    auto copy_chunk = [&](int chunk, int stage) {
        const uint32_t su = sb + stage * GSTG * 4;
        const uint4* aTh = A4h + (size_t)(m0 + crow) * U4DIM + chunk * 4 + cj;
        const uint4* aTl = A4l + (size_t)(m0 + crow) * U4DIM + chunk * 4 + cj;
        const uint4* bTh = B4h + (size_t)(n0 + crow) * U4DIM + chunk * 4 + cj;
        const uint4* bTl = B4l + (size_t)(n0 + crow) * U4DIM + chunk * 4 + cj;
        CPA16(su + (OAH + crow * GST + cj * 4) * 4, aTh);
        CPA16(su + (OAH + (crow + 64) * GST + cj * 4) * 4, aTh + (size_t)64 * U4DIM);
        CPA16(su + (OAL + crow * GST + cj * 4) * 4, aTl);
        CPA16(su + (OAL + (crow + 64) * GST + cj * 4) * 4, aTl + (size_t)64 * U4DIM);
        CPA16(su + (OBH + crow * GST + cj * 4) * 4, bTh);
        CPA16(su + (OBH + (crow + 64) * GST + cj * 4) * 4, bTh + (size_t)64 * U4DIM);
        CPA16(su + (OBL + crow * GST + cj * 4) * 4, bTl);
        CPA16(su + (OBL + (crow + 64) * GST + cj * 4) * 4, bTl + (size_t)64 * U4DIM);
    };

    auto compute_chunk = [&](int stage) {
        const uint32_t su = sb + stage * GSTG * 4;
#pragma unroll
        for (int kk = 0; kk < 2; kk++) {
            unsigned bh[4][4], bl[4][4];
#pragma unroll
            for (int tt = 0; tt < 4; tt++) {
                uint32_t brow = wn * 64 + tt * 16 + ((lane >> 4) << 3) + (lane & 7);
                uint32_t bj = kk * 2 + ((lane >> 3) & 1);
                uint32_t boff = (brow * GST + bj * 4) * 4;
                LDSM4(bh[tt][0], bh[tt][1], bh[tt][2], bh[tt][3], su + OBH * 4 + boff);
                LDSM4(bl[tt][0], bl[tt][1], bl[tt][2], bl[tt][3], su + OBL * 4 + boff);
            }
#pragma unroll
            for (int mi = 0; mi < 2; mi++) {
                unsigned ah[4], al[4];
                uint32_t arow = wm * 32 + mi * 16 + (lane & 15);
                uint32_t aj = kk * 2 + (lane >> 4);
                uint32_t aoff = (arow * GST + aj * 4) * 4;
                LDSM4(ah[0], ah[1], ah[2], ah[3], su + aoff);
                LDSM4(al[0], al[1], al[2], al[3], su + OAL * 4 + aoff);
#pragma unroll
                for (int tt = 0; tt < 4; tt++) {
#pragma unroll
                    for (int hf = 0; hf < 2; hf++) {
                        float* c = acc[mi][tt][hf];
                        mma16816(c, ah, bh[tt][2 * hf], bh[tt][2 * hf + 1]);
                        mma16816(c, ah, bl[tt][2 * hf], bl[tt][2 * hf + 1]);
                        mma16816(c, al, bh[tt][2 * hf], bh[tt][2 * hf + 1]);
                    }
                }
            }
        }
    };

    // prologue: fill stages 0 and 1
    copy_chunk(0, 0); CPCOMMIT();
    copy_chunk(1, 1); CPCOMMIT();

    for (int c = 0; c < 32; c++) {
        if (c < 31) { CPWAIT1(); } else { CPWAIT0(); }
        __syncthreads();          // chunk c visible; all warps done with compute(c-1)
        if (c + 2 < 32) {         // refill stage (c+2)%3 = (c-1)%3
            copy_chunk(c + 2, (c + 2) % 3);
            CPCOMMIT();
        }
        compute_chunk(c % 3);
    }

    // ---- epilogue ----
#pragma unroll
    for (int mi = 0; mi < 2; mi++) {
        int row = m0 + wm * 32 + mi * 16 + grp;
#pragma unroll
        for (int tt = 0; tt < 4; tt++) {
#pragma unroll
            for (int hf = 0; hf < 2; hf++) {
                int col = n0 + wn * 64 + tt * 16 + hf * 8 + 2 * q4;
                float b0 = bias[col], b1 = bias[col + 1];
                const float* a = acc[mi][tt][hf];
                float v0 = a[0] + b0, v1 = a[1] + b1;
                float v2 = a[2] + b0, v3 = a[3] + b1;
                if (mode == 0) {
                    *reinterpret_cast<float2*>(Cf + (size_t)row * DIM + col) =
                        make_float2(v0, v1);
                    *reinterpret_cast<float2*>(Cf + (size_t)(row + 8) * DIM + col) =
                        make_float2(v2, v3);
                } else {
                    unsigned h, l;
                    split2(v0 * scale, v1 * scale, h, l);
                    size_t o0 = (size_t)row * U32DIM + col / 2;
                    Ch[o0] = h; Cl[o0] = l;
                    split2(v2 * scale, v3 * scale, h, l);
                    size_t o1 = (size_t)(row + 8) * U32DIM + col / 2;
                    Ch[o1] = h; Cl[o1] = l;
                }
            }
        }
    }
}

// ---------------------------------------------------------------------------
// Flash attention: shift-free base-2 softmax (scores bounded, ex2 can't
// overflow; softmax shift-invariant).  q-tile 128 x 256 threads; kv-tile 64,
// 3-stage cp.async ring, ONE sync per tile.
// ---------------------------------------------------------------------------
#define AST 36
#define AQH 0
#define AQL 4608
#define AKH 9216
#define AKL 16128
#define AVH 23040
#define AVL 29952
#define KSTG 2304
#define ATTN_SMEM_BYTES (36864 * 4)   // 147456

__global__ __launch_bounds__(256, 1) void attn_kernel(
    const unsigned* __restrict__ Qhp, const unsigned* __restrict__ Qlp,
    const unsigned* __restrict__ Khp, const unsigned* __restrict__ Klp,
    const unsigned* __restrict__ Vhp, const unsigned* __restrict__ Vlp,
    unsigned* __restrict__ Ohg, unsigned* __restrict__ Olg)
{
    extern __shared__ unsigned smemA[];
    const uint32_t sb = smem_u32(smemA);

    const int tid  = threadIdx.x;
    const int lane = tid & 31;
    const int warp = tid >> 5;
    const int grp  = lane >> 2;
    const int q4   = lane & 3;

    const int bh = blockIdx.y;
    const int b  = bh >> 4;
    const int h  = bh & 15;
    const int q0 = blockIdx.x * 128;

    const uint4* Q4h = reinterpret_cast<const uint4*>(Qhp);
    const uint4* Q4l = reinterpret_cast<const uint4*>(Qlp);
    const uint4* K4h = reinterpret_cast<const uint4*>(Khp);
    const uint4* K4l = reinterpret_cast<const uint4*>(Klp);
    const uint4* V4h = reinterpret_cast<const uint4*>(Vhp);
    const uint4* V4l = reinterpret_cast<const uint4*>(Vlp);

    const size_t qrow0 = (size_t)(b * NQ + q0);
    const size_t hoff = (size_t)h * 8;

    // ---- Q copy (group 0, together with kv tile 0) ----
    {
        const int row8 = tid >> 3, j = tid & 7;
#pragma unroll
        for (int i = 0; i < 8; i++) {
            int r = ((i & 3) << 5) + row8;     // 0..127
            const uint4* src = ((i < 4) ? Q4h : Q4l) + (qrow0 + r) * U4ROW + hoff + j;
            uint32_t off = ((i < 4) ? AQH : AQL) + r * AST + j * 4;
            CPA16(sb + off * 4, src);
        }
    }

    auto copy_kv = [&](int tile, int stage) {
        const size_t krow0 = (size_t)(b * NKV + tile * 64);
        const int row8 = tid >> 3, j = tid & 7;
#pragma unroll
        for (int i = 0; i < 8; i++) {
            int r = ((i & 1) << 5) + row8;     // 0..63
            const uint4* src;
            uint32_t off;
            switch (i >> 1) {
                case 0:  src = K4h + (krow0 + r) * U4ROW + hoff + j; off = AKH; break;
                case 1:  src = K4l + (krow0 + r) * U4ROW + hoff + j; off = AKL; break;
                case 2:  src = V4h + (krow0 + r) * U4ROW + hoff + j; off = AVH; break;
                default: src = V4l + (krow0 + r) * U4ROW + hoff + j; off = AVL; break;
            }
            CPA16(sb + (off + stage * KSTG + r * AST + j * 4) * 4, src);
        }
    };

    copy_kv(0, 0); CPCOMMIT();
    copy_kv(1, 1); CPCOMMIT();

    float l0 = 0.f, l1 = 0.f;
    float o[8][4];
#pragma unroll
    for (int i = 0; i < 8; i++)
#pragma unroll
        for (int j = 0; j < 4; j++) o[i][j] = 0.f;

    const int r0w = warp * 16;

    for (int t = 0; t < 16; t++) {
        if (t < 14) { CPWAIT1(); } else { CPWAIT0(); }
        __syncthreads();
        if (t + 2 < 16) {
            copy_kv(t + 2, (t + 2) % 3);
            CPCOMMIT();
        }

        const int stg = t % 3;
        const uint32_t sKH = sb + (AKH + stg * KSTG) * 4;
        const uint32_t sKL = sb + (AKL + stg * KSTG) * 4;
        const uint32_t sVH = sb + (AVH + stg * KSTG) * 4;
        const uint32_t sVL = sb + (AVL + stg * KSTG) * 4;

        // ---- S = Q K^T (64 kv cols) ----
        float s[8][4];
#pragma unroll
        for (int i = 0; i < 8; i++)
#pragma unroll
            for (int j = 0; j < 4; j++) s[i][j] = 0.f;

#pragma unroll
        for (int dk = 0; dk < 4; dk++) {
            unsigned qh_[4], ql_[4];
            uint32_t arow = r0w + (lane & 15);
            uint32_t aj = 2 * dk + (lane >> 4);
            uint32_t aoff = (arow * AST + aj * 4) * 4;
            LDSM4(qh_[0], qh_[1], qh_[2], qh_[3], sb + aoff);
            LDSM4(ql_[0], ql_[1], ql_[2], ql_[3], sb + AQL * 4 + aoff);
#pragma unroll
            for (int tt = 0; tt < 4; tt++) {
                unsigned kh_[4], kl_[4];
                uint32_t brow = tt * 16 + ((lane >> 4) << 3) + (lane & 7);
                uint32_t bj = 2 * dk + ((lane >> 3) & 1);
                uint32_t boff = (brow * AST + bj * 4) * 4;
                LDSM4(kh_[0], kh_[1], kh_[2], kh_[3], sKH + boff);
                LDSM4(kl_[0], kl_[1], kl_[2], kl_[3], sKL + boff);
                mma16816(s[2 * tt],     qh_, kh_[0], kh_[1]);
                mma16816(s[2 * tt],     qh_, kl_[0], kl_[1]);
                mma16816(s[2 * tt],     ql_, kh_[0], kh_[1]);
                mma16816(s[2 * tt + 1], qh_, kh_[2], kh_[3]);
                mma16816(s[2 * tt + 1], qh_, kl_[2], kl_[3]);
                mma16816(s[2 * tt + 1], ql_, kh_[2], kh_[3]);
            }
        }

        // ---- P = 2^s, thread-local l accumulation ----
#pragma unroll
        for (int ni = 0; ni < 8; ni++) {
            s[ni][0] = ex2(s[ni][0]); l0 += s[ni][0];
            s[ni][1] = ex2(s[ni][1]); l0 += s[ni][1];
            s[ni][2] = ex2(s[ni][2]); l1 += s[ni][2];
            s[ni][3] = ex2(s[ni][3]); l1 += s[ni][3];
        }

        // ---- O += P @ V  (V via trans-LDSM) ----
#pragma unroll
        for (int st = 0; st < 4; st++) {
            unsigned ph[4], pl[4];
            split2(s[2 * st][0],     s[2 * st][1],     ph[0], pl[0]);
            split2(s[2 * st][2],     s[2 * st][3],     ph[1], pl[1]);
            split2(s[2 * st + 1][0], s[2 * st + 1][1], ph[2], pl[2]);
            split2(s[2 * st + 1][2], s[2 * st + 1][3], ph[3], pl[3]);
#pragma unroll
            for (int tt = 0; tt < 4; tt++) {
                unsigned vh_[4], vl_[4];
                uint32_t vrow = st * 16 + (((lane >> 3) & 1) << 3) + (lane & 7);
                uint32_t vj = 2 * tt + (lane >> 4);
                uint32_t voff = (vrow * AST + vj * 4) * 4;
                LDSM4T(vh_[0], vh_[1], vh_[2], vh_[3], sVH + voff);
                LDSM4T(vl_[0], vl_[1], vl_[2], vl_[3], sVL + voff);
                mma16816(o[2 * tt],     ph, vh_[0], vh_[1]);
                mma16816(o[2 * tt],     ph, vl_[0], vl_[1]);
                mma16816(o[2 * tt],     pl, vh_[0], vh_[1]);
                mma16816(o[2 * tt + 1], ph, vh_[2], vh_[3]);
                mma16816(o[2 * tt + 1], ph, vl_[2], vl_[3]);
                mma16816(o[2 * tt + 1], pl, vh_[2], vh_[3]);
            }
        }
    }

    // ---- one-time l reduction + epilogue (pre-split O) ----
    l0 += __shfl_xor_sync(0xffffffffu, l0, 1);
    l0 += __shfl_xor_sync(0xffffffffu, l0, 2);
    l1 += __shfl_xor_sync(0xffffffffu, l1, 1);
    l1 += __shfl_xor_sync(0xffffffffu, l1, 2);
    float inv0 = 1.f / l0, inv1 = 1.f / l1;
    const int r0 = q0 + warp * 16 + grp;
#pragma unroll
    for (int ni = 0; ni < 8; ni++) {
        int c = ni * 8 + 2 * q4;
        unsigned hh, ll;
        split2(o[ni][0] * inv0, o[ni][1] * inv0, hh, ll);
        size_t o0 = (size_t)(b * NQ + r0) * U32DIM + h * 32 + c / 2;
        Ohg[o0] = hh; Olg[o0] = ll;
        split2(o[ni][2] * inv1, o[ni][3] * inv1, hh, ll);
        size_t o1 = (size_t)(b * NQ + r0 + 8) * U32DIM + h * 32 + c / 2;
        Ohg[o1] = hh; Olg[o1] = ll;
    }
}

// ---------------------------------------------------------------------------
// launch
// ---------------------------------------------------------------------------
extern "C" void kernel_launch(void* const* d_in, const int* in_sizes, int n_in,
                              void* d_out, int out_size)
{
    (void)in_sizes; (void)n_in; (void)out_size;
    const float* x   = (const float*)d_in[0];
    const float* ctx = (const float*)d_in[1];
    const float* Wq  = (const float*)d_in[2];
    const float* bq  = (const float*)d_in[3];
    const float* Wk  = (const float*)d_in[4];
    const float* bk  = (const float*)d_in[5];
    const float* Wv  = (const float*)d_in[6];
    const float* bv  = (const float*)d_in[7];
    const float* Wo  = (const float*)d_in[8];
    const float* bo  = (const float*)d_in[9];
    float* out = (float*)d_out;

    unsigned *xh, *xl, *ch, *cl;
    unsigned *wqh, *wql, *wkh, *wkl, *wvh, *wvl, *woh, *wol;
    unsigned *qh, *ql, *kh, *kl, *vh, *vl, *oh, *ol;
    cudaGetSymbolAddress((void**)&xh, g_xh);   cudaGetSymbolAddress((void**)&xl, g_xl);
    cudaGetSymbolAddress((void**)&ch, g_ch);   cudaGetSymbolAddress((void**)&cl, g_cl);
    cudaGetSymbolAddress((void**)&wqh, g_Wqh); cudaGetSymbolAddress((void**)&wql, g_Wql);
    cudaGetSymbolAddress((void**)&wkh, g_Wkh); cudaGetSymbolAddress((void**)&wkl, g_Wkl);
    cudaGetSymbolAddress((void**)&wvh, g_Wvh); cudaGetSymbolAddress((void**)&wvl, g_Wvl);
    cudaGetSymbolAddress((void**)&woh, g_Woh); cudaGetSymbolAddress((void**)&wol, g_Wol);
    cudaGetSymbolAddress((void**)&qh, g_Qh);   cudaGetSymbolAddress((void**)&ql, g_Ql);
    cudaGetSymbolAddress((void**)&kh, g_Kh);   cudaGetSymbolAddress((void**)&kl, g_Kl);
    cudaGetSymbolAddress((void**)&vh, g_Vh);   cudaGetSymbolAddress((void**)&vl, g_Vl);
    cudaGetSymbolAddress((void**)&oh, g_Oh);   cudaGetSymbolAddress((void**)&ol, g_Ol);

    cudaFuncSetAttribute(gemm_bf16_kernel,
                         cudaFuncAttributeMaxDynamicSharedMemorySize, GSMEM_BYTES);
    cudaFuncSetAttribute(attn_kernel,
                         cudaFuncAttributeMaxDynamicSharedMemorySize, ATTN_SMEM_BYTES);

    const int n2 = MROWS * U32DIM;
    const float QSCALE = 0.125f * 1.44269504088896340736f;
    dim3 gblk(256);
    dim3 ggrid(DIM / 128, MROWS / 128);   // (8, 64)

    split_kernel<<<n2 / 256, 256>>>(x,   xh, xl, n2);
    split_kernel<<<n2 / 256, 256>>>(ctx, ch, cl, n2);
    tsplit_kernel<<<dim3(16, 16), 256>>>(Wq, wqh, wql);
    tsplit_kernel<<<dim3(16, 16), 256>>>(Wk, wkh, wkl);
    tsplit_kernel<<<dim3(16, 16), 256>>>(Wv, wvh, wvl);
    gemm_bf16_kernel<<<ggrid, gblk, GSMEM_BYTES>>>(
        xh, xl, wqh, wql, bq, nullptr, qh, ql, QSCALE, 1);
    gemm_bf16_kernel<<<ggrid, gblk, GSMEM_BYTES>>>(
        ch, cl, wkh, wkl, bk, nullptr, kh, kl, 1.f, 1);
    gemm_bf16_kernel<<<ggrid, gblk, GSMEM_BYTES>>>(
        ch, cl, wvh, wvl, bv, nullptr, vh, vl, 1.f, 1);
    tsplit_kernel<<<dim3(16, 16), 256>>>(Wo, woh, wol);
    attn_kernel<<<dim3(NQ / 128, BATCH * NHEADS), 256, ATTN_SMEM_BYTES>>>(
        qh, ql, kh, kl, vh, vl, oh, ol);
    gemm_bf16_kernel<<<ggrid, gblk, GSMEM_BYTES>>>(
        oh, ol, woh, wol, bo, out, nullptr, nullptr, 1.f, 0);
}

// round 8
// speedup vs baseline: 1.1530x; 1.1530x over previous
#include <cuda_runtime.h>
#include <cuda_bf16.h>
#include <cstdint>

// Problem constants
#define BATCH 8
#define NQ 1024
#define NKV 1024
#define DIM 1024
#define NHEADS 16
#define HDIM 64
#define MROWS (BATCH * NQ)     // 8192
#define U32DIM (DIM / 2)       // 512 u32 per row
#define U4DIM (DIM / 8)        // 128 uint4 per row
#define U4ROW (U32DIM / 4)     // 128

// ---------------------------------------------------------------------------
// Scratch (device globals; allocation is not allowed)
// ---------------------------------------------------------------------------
__device__ unsigned g_xh[MROWS * U32DIM], g_xl[MROWS * U32DIM];
__device__ unsigned g_ch[MROWS * U32DIM], g_cl[MROWS * U32DIM];
__device__ unsigned g_Wqh[DIM * U32DIM], g_Wql[DIM * U32DIM];
__device__ unsigned g_Wkh[DIM * U32DIM], g_Wkl[DIM * U32DIM];
__device__ unsigned g_Wvh[DIM * U32DIM], g_Wvl[DIM * U32DIM];
__device__ unsigned g_Woh[DIM * U32DIM], g_Wol[DIM * U32DIM];
__device__ unsigned g_Qh[MROWS * U32DIM], g_Ql[MROWS * U32DIM];
__device__ unsigned g_Kh[MROWS * U32DIM], g_Kl[MROWS * U32DIM];
__device__ unsigned g_Vh[MROWS * U32DIM], g_Vl[MROWS * U32DIM];
__device__ unsigned g_Oh[MROWS * U32DIM], g_Ol[MROWS * U32DIM];

// ---------------------------------------------------------------------------
// helpers
// ---------------------------------------------------------------------------
__device__ __forceinline__ void split2(float x, float y, unsigned &hi, unsigned &lo) {
    __nv_bfloat162 h = __floats2bfloat162_rn(x, y);
    float hx = __bfloat162float(h.x);
    float hy = __bfloat162float(h.y);
    __nv_bfloat162 l = __floats2bfloat162_rn(x - hx, y - hy);
    hi = *reinterpret_cast<unsigned*>(&h);
    lo = *reinterpret_cast<unsigned*>(&l);
}

__device__ __forceinline__ void mma16816(float* c, const unsigned* a, unsigned b0, unsigned b1) {
    asm volatile(
        "mma.sync.aligned.m16n8k16.row.col.f32.bf16.bf16.f32 "
        "{%0,%1,%2,%3}, {%4,%5,%6,%7}, {%8,%9}, {%0,%1,%2,%3};\n"
        : "+f"(c[0]), "+f"(c[1]), "+f"(c[2]), "+f"(c[3])
        : "r"(a[0]), "r"(a[1]), "r"(a[2]), "r"(a[3]), "r"(b0), "r"(b1));
}

__device__ __forceinline__ float ex2(float x) {
    float r;
    asm("ex2.approx.f32 %0, %1;" : "=f"(r) : "f"(x));
    return r;
}

__device__ __forceinline__ uint32_t smem_u32(const void* p) {
    uint32_t a;
    asm("{ .reg .u64 t; cvta.to.shared.u64 t, %1; cvt.u32.u64 %0, t; }" : "=r"(a) : "l"(p));
    return a;
}

#define LDSM4(r0, r1, r2, r3, addr) \
    asm volatile("ldmatrix.sync.aligned.m8n8.x4.shared.b16 {%0,%1,%2,%3}, [%4];" \
                 : "=r"(r0), "=r"(r1), "=r"(r2), "=r"(r3) : "r"(addr))

#define LDSM4T(r0, r1, r2, r3, addr) \
    asm volatile("ldmatrix.sync.aligned.m8n8.x4.trans.shared.b16 {%0,%1,%2,%3}, [%4];" \
                 : "=r"(r0), "=r"(r1), "=r"(r2), "=r"(r3) : "r"(addr))

#define CPA16(dst, src) \
    asm volatile("cp.async.cg.shared.global [%0], [%1], 16;" :: "r"(dst), "l"(src))
#define CPCOMMIT() asm volatile("cp.async.commit_group;")
#define CPWAIT1()  asm volatile("cp.async.wait_group 1;")
#define CPWAIT0()  asm volatile("cp.async.wait_group 0;")

// ---------------------------------------------------------------------------
// one-shot conversions
// ---------------------------------------------------------------------------
__global__ __launch_bounds__(256) void split_kernel(
    const float* __restrict__ src, unsigned* __restrict__ hi,
    unsigned* __restrict__ lo, int n2)
{
    int i = blockIdx.x * 256 + threadIdx.x;
    if (i < n2) {
        float2 v = reinterpret_cast<const float2*>(src)[i];
        unsigned h, l;
        split2(v.x, v.y, h, l);
        hi[i] = h;
        lo[i] = l;
    }
}

// W[k][n] -> Wt[n][k] as bf16 hi/lo (u32 = k-pair)
__global__ __launch_bounds__(256) void tsplit_kernel(
    const float* __restrict__ W, unsigned* __restrict__ Th, unsigned* __restrict__ Tl)
{
    __shared__ float t[64][65];
    const int k0 = blockIdx.y * 64, n0 = blockIdx.x * 64;
#pragma unroll
    for (int i = 0; i < 16; i++) {
        int idx = threadIdx.x + i * 256;
        int k = idx >> 6, n = idx & 63;
        t[k][n] = W[(size_t)(k0 + k) * DIM + n0 + n];
    }
    __syncthreads();
#pragma unroll
    for (int i = 0; i < 8; i++) {
        int idx = threadIdx.x + i * 256;
        int n = idx >> 5, kp = idx & 31;
        unsigned h, l;
        split2(t[2 * kp][n], t[2 * kp + 1][n], h, l);
        size_t o = (size_t)(n0 + n) * U32DIM + k0 / 2 + kp;
        Th[o] = h;
        Tl[o] = l;
    }
}

// ---------------------------------------------------------------------------
// GEMM (pre-split bf16, 3-stage cp.async, XOR-swizzled smem, ONE sync/chunk):
//   C[8192,1024] = A @ Wt^T + bias.  Block 128x128, k-chunk 32, 512 threads
//   (16 warps, warp tile 32x32), 1 CTA/SM.  bf16x3 accumulate.
//   smem row = 16 u32 (64B), chunk swizzle: cj ^= (row>>1)&3  (verified
//   conflict-free for 16B stores and 8-row ldmatrix).
//   mode 0: Cf = fp32.  mode 1: split(val*scale) -> Ch/Cl.
// ---------------------------------------------------------------------------
#define OAH 0
#define OAL 2048
#define OBH 4096
#define OBL 6144
#define GSTG 8192     // u32 per stage (32KB)
#define GSMEM_BYTES (3 * GSTG * 4)   // 98304

__device__ __forceinline__ uint32_t gsw(uint32_t row, uint32_t cj) {
    return (row * 16 + (cj ^ ((row >> 1) & 3)) * 4) * 4;   // byte offset
}

__global__ __launch_bounds__(512, 1) void gemm_bf16_kernel(
    const unsigned* __restrict__ Ahp, const unsigned* __restrict__ Alp,
    const unsigned* __restrict__ Bhp, const unsigned* __restrict__ Blp,
    const float* __restrict__ bias, float* __restrict__ Cf,
    unsigned* __restrict__ Ch, unsigned* __restrict__ Cl,
    float scale, int mode)
{
    extern __shared__ unsigned gsm[];
    const uint32_t sb = smem_u32(gsm);

    const int tid  = threadIdx.x;
    const int lane = tid & 31;
    const int warp = tid >> 5;    // 0..15
    const int grp  = lane >> 2;
    const int q4   = lane & 3;
    const int wm   = warp >> 2;   // 0..3 (32-row group)
    const int wn   = warp & 3;    // 0..3 (32-col group)
    const int m0 = blockIdx.y * 128;
    const int n0 = blockIdx.x * 128;

    const uint4* A4h = reinterpret_cast<const uint4*>(Ahp);
    const uint4* A4l = reinterpret_cast<const uint4*>(Alp);
    const uint4* B4h = reinterpret_cast<const uint4*>(Bhp);
    const uint4* B4l = reinterpret_cast<const uint4*>(Blp);

    float acc[2][2][2][4];   // [mi][tt][hf][4]
#pragma unroll
    for (int a = 0; a < 2; a++)
#pragma unroll
        for (int b = 0; b < 2; b++)
#pragma unroll
            for (int c = 0; c < 2; c++)
#pragma unroll
                for (int d = 0; d < 4; d++) acc[a][b][c][d] = 0.f;

    const int crow = tid >> 2;          // 0..127
    const int cj   = tid & 3;

    auto copy_chunk = [&](int chunk, int stage) {
        const uint32_t su = sb + stage * GSTG * 4;
        const uint32_t doff = gsw(crow, cj);
        CPA16(su + OAH * 4 + doff, A4h + (size_t)(m0 + crow) * U4DIM + chunk * 4 + cj);
        CPA16(su + OAL * 4 + doff, A4l + (size_t)(m0 + crow) * U4DIM + chunk * 4 + cj);
        CPA16(su + OBH * 4 + doff, B4h + (size_t)(n0 + crow) * U4DIM + chunk * 4 + cj);
        CPA16(su + OBL * 4 + doff, B4l + (size_t)(n0 + crow) * U4DIM + chunk * 4 + cj);
    };

    auto compute_chunk = [&](int stage) {
        const uint32_t su = sb + stage * GSTG * 4;
#pragma unroll
        for (int kk = 0; kk < 2; kk++) {
            unsigned bh[2][4], bl[2][4];
#pragma unroll
            for (int tt = 0; tt < 2; tt++) {
                uint32_t brow = wn * 32 + tt * 16 + ((lane >> 4) << 3) + (lane & 7);
                uint32_t bj = kk * 2 + ((lane >> 3) & 1);
                uint32_t boff = gsw(brow, bj);
                LDSM4(bh[tt][0], bh[tt][1], bh[tt][2], bh[tt][3], su + OBH * 4 + boff);
                LDSM4(bl[tt][0], bl[tt][1], bl[tt][2], bl[tt][3], su + OBL * 4 + boff);
            }
#pragma unroll
            for (int mi = 0; mi < 2; mi++) {
                unsigned ah[4], al[4];
                uint32_t arow = wm * 32 + mi * 16 + (lane & 15);
                uint32_t aj = kk * 2 + (lane >> 4);
                uint32_t aoff = gsw(arow, aj);
                LDSM4(ah[0], ah[1], ah[2], ah[3], su + OAH * 4 + aoff);
                LDSM4(al[0], al[1], al[2], al[3], su + OAL * 4 + aoff);
#pragma unroll
                for (int tt = 0; tt < 2; tt++) {
#pragma unroll
                    for (int hf = 0; hf < 2; hf++) {
                        float* c = acc[mi][tt][hf];
                        mma16816(c, ah, bh[tt][2 * hf], bh[tt][2 * hf + 1]);
                        mma16816(c, ah, bl[tt][2 * hf], bl[tt][2 * hf + 1]);
                        mma16816(c, al, bh[tt][2 * hf], bh[tt][2 * hf + 1]);
                    }
                }
            }
        }
    };

    // prologue: fill stages 0 and 1
    copy_chunk(0, 0); CPCOMMIT();
    copy_chunk(1, 1); CPCOMMIT();

    for (int c = 0; c < 32; c++) {
        if (c < 31) { CPWAIT1(); } else { CPWAIT0(); }
        __syncthreads();          // chunk c visible; all warps done with compute(c-1)
        if (c + 2 < 32) {         // refill stage (c+2)%3 = (c-1)%3
            copy_chunk(c + 2, (c + 2) % 3);
            CPCOMMIT();
        }
        compute_chunk(c % 3);
    }

    // ---- epilogue ----
#pragma unroll
    for (int mi = 0; mi < 2; mi++) {
        int row = m0 + wm * 32 + mi * 16 + grp;
#pragma unroll
        for (int tt = 0; tt < 2; tt++) {
#pragma unroll
            for (int hf = 0; hf < 2; hf++) {
                int col = n0 + wn * 32 + tt * 16 + hf * 8 + 2 * q4;
                float b0 = bias[col], b1 = bias[col + 1];
                const float* a = acc[mi][tt][hf];
                float v0 = a[0] + b0, v1 = a[1] + b1;
                float v2 = a[2] + b0, v3 = a[3] + b1;
                if (mode == 0) {
                    *reinterpret_cast<float2*>(Cf + (size_t)row * DIM + col) =
                        make_float2(v0, v1);
                    *reinterpret_cast<float2*>(Cf + (size_t)(row + 8) * DIM + col) =
                        make_float2(v2, v3);
                } else {
                    unsigned h, l;
                    split2(v0 * scale, v1 * scale, h, l);
                    size_t o0 = (size_t)row * U32DIM + col / 2;
                    Ch[o0] = h; Cl[o0] = l;
                    split2(v2 * scale, v3 * scale, h, l);
                    size_t o1 = (size_t)(row + 8) * U32DIM + col / 2;
                    Ch[o1] = h; Cl[o1] = l;
                }
            }
        }
    }
}

// ---------------------------------------------------------------------------
// Flash attention (exact round-6 winner): shift-free base-2 softmax,
// q-tile 128 x 256 threads; kv-tile 64, 2-stage cp.async ring.
// ---------------------------------------------------------------------------
#define AST 36
#define AQH 0
#define AQL 4608
#define AKH 9216
#define AKL 13824
#define AVH 18432
#define AVL 23040
#define KSTG 2304
#define ATTN_SMEM_BYTES (27648 * 4)   // 110592

__global__ __launch_bounds__(256) void attn_kernel(
    const unsigned* __restrict__ Qhp, const unsigned* __restrict__ Qlp,
    const unsigned* __restrict__ Khp, const unsigned* __restrict__ Klp,
    const unsigned* __restrict__ Vhp, const unsigned* __restrict__ Vlp,
    unsigned* __restrict__ Ohg, unsigned* __restrict__ Olg)
{
    extern __shared__ unsigned smemA[];
    const uint32_t sb = smem_u32(smemA);

    const int tid  = threadIdx.x;
    const int lane = tid & 31;
    const int warp = tid >> 5;
    const int grp  = lane >> 2;
    const int q4   = lane & 3;

    const int bh = blockIdx.y;
    const int b  = bh >> 4;
    const int h  = bh & 15;
    const int q0 = blockIdx.x * 128;

    const uint4* Q4h = reinterpret_cast<const uint4*>(Qhp);
    const uint4* Q4l = reinterpret_cast<const uint4*>(Qlp);
    const uint4* K4h = reinterpret_cast<const uint4*>(Khp);
    const uint4* K4l = reinterpret_cast<const uint4*>(Klp);
    const uint4* V4h = reinterpret_cast<const uint4*>(Vhp);
    const uint4* V4l = reinterpret_cast<const uint4*>(Vlp);

    const size_t qrow0 = (size_t)(b * NQ + q0);
    const size_t hoff = (size_t)h * 8;

    // ---- Q copy ----
    {
        const int row8 = tid >> 3, j = tid & 7;
#pragma unroll
        for (int i = 0; i < 8; i++) {
            int r = ((i & 3) << 5) + row8;     // 0..127
            const uint4* src = ((i < 4) ? Q4h : Q4l) + (qrow0 + r) * U4ROW + hoff + j;
            uint32_t off = ((i < 4) ? AQH : AQL) + r * AST + j * 4;
            CPA16(sb + off * 4, src);
        }
    }

    auto copy_kv = [&](int tile, int stage) {
        const size_t krow0 = (size_t)(b * NKV + tile * 64);
        const int row8 = tid >> 3, j = tid & 7;
#pragma unroll
        for (int i = 0; i < 8; i++) {
            int r = ((i & 1) << 5) + row8;     // 0..63
            const uint4* src;
            uint32_t off;
            switch (i >> 1) {
                case 0:  src = K4h + (krow0 + r) * U4ROW + hoff + j; off = AKH; break;
                case 1:  src = K4l + (krow0 + r) * U4ROW + hoff + j; off = AKL; break;
                case 2:  src = V4h + (krow0 + r) * U4ROW + hoff + j; off = AVH; break;
                default: src = V4l + (krow0 + r) * U4ROW + hoff + j; off = AVL; break;
            }
            CPA16(sb + (off + stage * KSTG + r * AST + j * 4) * 4, src);
        }
    };

    copy_kv(0, 0);
    CPCOMMIT();

    float l0 = 0.f, l1 = 0.f;
    float o[8][4];
#pragma unroll
    for (int i = 0; i < 8; i++)
#pragma unroll
        for (int j = 0; j < 4; j++) o[i][j] = 0.f;

    const int r0w = warp * 16;

    for (int t = 0; t < 16; t++) {
        if (t < 15) {
            copy_kv(t + 1, (t + 1) & 1);
            CPCOMMIT();
            CPWAIT1();
        } else {
            CPWAIT0();
        }
        __syncthreads();

        const uint32_t sKH = sb + (AKH + (t & 1) * KSTG) * 4;
        const uint32_t sKL = sb + (AKL + (t & 1) * KSTG) * 4;
        const uint32_t sVH = sb + (AVH + (t & 1) * KSTG) * 4;
        const uint32_t sVL = sb + (AVL + (t & 1) * KSTG) * 4;

        // ---- S = Q K^T (64 kv cols) ----
        float s[8][4];
#pragma unroll
        for (int i = 0; i < 8; i++)
#pragma unroll
            for (int j = 0; j < 4; j++) s[i][j] = 0.f;

#pragma unroll
        for (int dk = 0; dk < 4; dk++) {
            unsigned qh_[4], ql_[4];
            uint32_t arow = r0w + (lane & 15);
            uint32_t aj = 2 * dk + (lane >> 4);
            uint32_t aoff = (arow * AST + aj * 4) * 4;
            LDSM4(qh_[0], qh_[1], qh_[2], qh_[3], sb + aoff);
            LDSM4(ql_[0], ql_[1], ql_[2], ql_[3], sb + AQL * 4 + aoff);
#pragma unroll
            for (int tt = 0; tt < 4; tt++) {
                unsigned kh_[4], kl_[4];
                uint32_t brow = tt * 16 + ((lane >> 4) << 3) + (lane & 7);
                uint32_t bj = 2 * dk + ((lane >> 3) & 1);
                uint32_t boff = (brow * AST + bj * 4) * 4;
                LDSM4(kh_[0], kh_[1], kh_[2], kh_[3], sKH + boff);
                LDSM4(kl_[0], kl_[1], kl_[2], kl_[3], sKL + boff);
                mma16816(s[2 * tt],     qh_, kh_[0], kh_[1]);
                mma16816(s[2 * tt],     qh_, kl_[0], kl_[1]);
                mma16816(s[2 * tt],     ql_, kh_[0], kh_[1]);
                mma16816(s[2 * tt + 1], qh_, kh_[2], kh_[3]);
                mma16816(s[2 * tt + 1], qh_, kl_[2], kl_[3]);
                mma16816(s[2 * tt + 1], ql_, kh_[2], kh_[3]);
            }
        }

        // ---- P = 2^s, thread-local l accumulation ----
#pragma unroll
        for (int ni = 0; ni < 8; ni++) {
            s[ni][0] = ex2(s[ni][0]); l0 += s[ni][0];
            s[ni][1] = ex2(s[ni][1]); l0 += s[ni][1];
            s[ni][2] = ex2(s[ni][2]); l1 += s[ni][2];
            s[ni][3] = ex2(s[ni][3]); l1 += s[ni][3];
        }

        // ---- O += P @ V  (V via trans-LDSM) ----
#pragma unroll
        for (int st = 0; st < 4; st++) {
            unsigned ph[4], pl[4];
            split2(s[2 * st][0],     s[2 * st][1],     ph[0], pl[0]);
            split2(s[2 * st][2],     s[2 * st][3],     ph[1], pl[1]);
            split2(s[2 * st + 1][0], s[2 * st + 1][1], ph[2], pl[2]);
            split2(s[2 * st + 1][2], s[2 * st + 1][3], ph[3], pl[3]);
#pragma unroll
            for (int tt = 0; tt < 4; tt++) {
                unsigned vh_[4], vl_[4];
                uint32_t vrow = st * 16 + (((lane >> 3) & 1) << 3) + (lane & 7);
                uint32_t vj = 2 * tt + (lane >> 4);
                uint32_t voff = (vrow * AST + vj * 4) * 4;
                LDSM4T(vh_[0], vh_[1], vh_[2], vh_[3], sVH + voff);
                LDSM4T(vl_[0], vl_[1], vl_[2], vl_[3], sVL + voff);
                mma16816(o[2 * tt],     ph, vh_[0], vh_[1]);
                mma16816(o[2 * tt],     ph, vl_[0], vl_[1]);
                mma16816(o[2 * tt],     pl, vh_[0], vh_[1]);
                mma16816(o[2 * tt + 1], ph, vh_[2], vh_[3]);
                mma16816(o[2 * tt + 1], ph, vl_[2], vl_[3]);
                mma16816(o[2 * tt + 1], pl, vh_[2], vh_[3]);
            }
        }
        __syncthreads();
    }

    // ---- one-time l reduction + epilogue (pre-split O) ----
    l0 += __shfl_xor_sync(0xffffffffu, l0, 1);
    l0 += __shfl_xor_sync(0xffffffffu, l0, 2);
    l1 += __shfl_xor_sync(0xffffffffu, l1, 1);
    l1 += __shfl_xor_sync(0xffffffffu, l1, 2);
    float inv0 = 1.f / l0, inv1 = 1.f / l1;
    const int r0 = q0 + warp * 16 + grp;
#pragma unroll
    for (int ni = 0; ni < 8; ni++) {
        int c = ni * 8 + 2 * q4;
        unsigned hh, ll;
        split2(o[ni][0] * inv0, o[ni][1] * inv0, hh, ll);
        size_t o0 = (size_t)(b * NQ + r0) * U32DIM + h * 32 + c / 2;
        Ohg[o0] = hh; Olg[o0] = ll;
        split2(o[ni][2] * inv1, o[ni][3] * inv1, hh, ll);
        size_t o1 = (size_t)(b * NQ + r0 + 8) * U32DIM + h * 32 + c / 2;
        Ohg[o1] = hh; Olg[o1] = ll;
    }
}

// ---------------------------------------------------------------------------
// launch
// ---------------------------------------------------------------------------
extern "C" void kernel_launch(void* const* d_in, const int* in_sizes, int n_in,
                              void* d_out, int out_size)
{
    (void)in_sizes; (void)n_in; (void)out_size;
    const float* x   = (const float*)d_in[0];
    const float* ctx = (const float*)d_in[1];
    const float* Wq  = (const float*)d_in[2];
    const float* bq  = (const float*)d_in[3];
    const float* Wk  = (const float*)d_in[4];
    const float* bk  = (const float*)d_in[5];
    const float* Wv  = (const float*)d_in[6];
    const float* bv  = (const float*)d_in[7];
    const float* Wo  = (const float*)d_in[8];
    const float* bo  = (const float*)d_in[9];
    float* out = (float*)d_out;

    unsigned *xh, *xl, *ch, *cl;
    unsigned *wqh, *wql, *wkh, *wkl, *wvh, *wvl, *woh, *wol;
    unsigned *qh, *ql, *kh, *kl, *vh, *vl, *oh, *ol;
    cudaGetSymbolAddress((void**)&xh, g_xh);   cudaGetSymbolAddress((void**)&xl, g_xl);
    cudaGetSymbolAddress((void**)&ch, g_ch);   cudaGetSymbolAddress((void**)&cl, g_cl);
    cudaGetSymbolAddress((void**)&wqh, g_Wqh); cudaGetSymbolAddress((void**)&wql, g_Wql);
    cudaGetSymbolAddress((void**)&wkh, g_Wkh); cudaGetSymbolAddress((void**)&wkl, g_Wkl);
    cudaGetSymbolAddress((void**)&wvh, g_Wvh); cudaGetSymbolAddress((void**)&wvl, g_Wvl);
    cudaGetSymbolAddress((void**)&woh, g_Woh); cudaGetSymbolAddress((void**)&wol, g_Wol);
    cudaGetSymbolAddress((void**)&qh, g_Qh);   cudaGetSymbolAddress((void**)&ql, g_Ql);
    cudaGetSymbolAddress((void**)&kh, g_Kh);   cudaGetSymbolAddress((void**)&kl, g_Kl);
    cudaGetSymbolAddress((void**)&vh, g_Vh);   cudaGetSymbolAddress((void**)&vl, g_Vl);
    cudaGetSymbolAddress((void**)&oh, g_Oh);   cudaGetSymbolAddress((void**)&ol, g_Ol);

    cudaFuncSetAttribute(gemm_bf16_kernel,
                         cudaFuncAttributeMaxDynamicSharedMemorySize, GSMEM_BYTES);
    cudaFuncSetAttribute(attn_kernel,
                         cudaFuncAttributeMaxDynamicSharedMemorySize, ATTN_SMEM_BYTES);

    const int n2 = MROWS * U32DIM;
    const float QSCALE = 0.125f * 1.44269504088896340736f;
    dim3 gblk(512);
    dim3 ggrid(DIM / 128, MROWS / 128);   // (8, 64)

    split_kernel<<<n2 / 256, 256>>>(x,   xh, xl, n2);
    split_kernel<<<n2 / 256, 256>>>(ctx, ch, cl, n2);
    tsplit_kernel<<<dim3(16, 16), 256>>>(Wq, wqh, wql);
    tsplit_kernel<<<dim3(16, 16), 256>>>(Wk, wkh, wkl);
    tsplit_kernel<<<dim3(16, 16), 256>>>(Wv, wvh, wvl);
    gemm_bf16_kernel<<<ggrid, gblk, GSMEM_BYTES>>>(
        xh, xl, wqh, wql, bq, nullptr, qh, ql, QSCALE, 1);
    gemm_bf16_kernel<<<ggrid, gblk, GSMEM_BYTES>>>(
        ch, cl, wkh, wkl, bk, nullptr, kh, kl, 1.f, 1);
    gemm_bf16_kernel<<<ggrid, gblk, GSMEM_BYTES>>>(
        ch, cl, wvh, wvl, bv, nullptr, vh, vl, 1.f, 1);
    tsplit_kernel<<<dim3(16, 16), 256>>>(Wo, woh, wol);
    attn_kernel<<<dim3(NQ / 128, BATCH * NHEADS), 256, ATTN_SMEM_BYTES>>>(
        qh, ql, kh, kl, vh, vl, oh, ol);
    gemm_bf16_kernel<<<ggrid, gblk, GSMEM_BYTES>>>(
        oh, ol, woh, wol, bo, out, nullptr, nullptr, 1.f, 0);
}

// round 9
// speedup vs baseline: 1.2529x; 1.0866x over previous
#include <cuda_runtime.h>
#include <cuda_bf16.h>
#include <cstdint>

// Problem constants
#define BATCH 8
#define NQ 1024
#define NKV 1024
#define DIM 1024
#define NHEADS 16
#define HDIM 64
#define MROWS (BATCH * NQ)     // 8192
#define U32DIM (DIM / 2)       // 512 u32 per row
#define U4DIM (DIM / 8)        // 128 uint4 per row
#define U4ROW (U32DIM / 4)     // 128

// ---------------------------------------------------------------------------
// Scratch (device globals; allocation is not allowed)
// ---------------------------------------------------------------------------
__device__ unsigned g_xh[MROWS * U32DIM], g_xl[MROWS * U32DIM];
__device__ unsigned g_ch[MROWS * U32DIM], g_cl[MROWS * U32DIM];
__device__ unsigned g_Wqh[DIM * U32DIM], g_Wql[DIM * U32DIM];
__device__ unsigned g_Wkh[DIM * U32DIM], g_Wkl[DIM * U32DIM];
__device__ unsigned g_Wvh[DIM * U32DIM], g_Wvl[DIM * U32DIM];
__device__ unsigned g_Woh[DIM * U32DIM], g_Wol[DIM * U32DIM];
__device__ unsigned g_Qh[MROWS * U32DIM], g_Ql[MROWS * U32DIM];
__device__ unsigned g_Kh[MROWS * U32DIM], g_Kl[MROWS * U32DIM];
__device__ unsigned g_Vh[MROWS * U32DIM], g_Vl[MROWS * U32DIM];
__device__ unsigned g_Oh[MROWS * U32DIM], g_Ol[MROWS * U32DIM];

// ---------------------------------------------------------------------------
// helpers
// ---------------------------------------------------------------------------
__device__ __forceinline__ void split2(float x, float y, unsigned &hi, unsigned &lo) {
    __nv_bfloat162 h = __floats2bfloat162_rn(x, y);
    float hx = __bfloat162float(h.x);
    float hy = __bfloat162float(h.y);
    __nv_bfloat162 l = __floats2bfloat162_rn(x - hx, y - hy);
    hi = *reinterpret_cast<unsigned*>(&h);
    lo = *reinterpret_cast<unsigned*>(&l);
}

__device__ __forceinline__ void mma16816(float* c, const unsigned* a, unsigned b0, unsigned b1) {
    asm volatile(
        "mma.sync.aligned.m16n8k16.row.col.f32.bf16.bf16.f32 "
        "{%0,%1,%2,%3}, {%4,%5,%6,%7}, {%8,%9}, {%0,%1,%2,%3};\n"
        : "+f"(c[0]), "+f"(c[1]), "+f"(c[2]), "+f"(c[3])
        : "r"(a[0]), "r"(a[1]), "r"(a[2]), "r"(a[3]), "r"(b0), "r"(b1));
}

__device__ __forceinline__ float ex2(float x) {
    float r;
    asm("ex2.approx.f32 %0, %1;" : "=f"(r) : "f"(x));
    return r;
}

__device__ __forceinline__ uint32_t smem_u32(const void* p) {
    uint32_t a;
    asm("{ .reg .u64 t; cvta.to.shared.u64 t, %1; cvt.u32.u64 %0, t; }" : "=r"(a) : "l"(p));
    return a;
}

#define LDSM4(r0, r1, r2, r3, addr) \
    asm volatile("ldmatrix.sync.aligned.m8n8.x4.shared.b16 {%0,%1,%2,%3}, [%4];" \
                 : "=r"(r0), "=r"(r1), "=r"(r2), "=r"(r3) : "r"(addr))

#define LDSM4T(r0, r1, r2, r3, addr) \
    asm volatile("ldmatrix.sync.aligned.m8n8.x4.trans.shared.b16 {%0,%1,%2,%3}, [%4];" \
                 : "=r"(r0), "=r"(r1), "=r"(r2), "=r"(r3) : "r"(addr))

#define CPA16(dst, src) \
    asm volatile("cp.async.cg.shared.global [%0], [%1], 16;" :: "r"(dst), "l"(src))
#define CPCOMMIT() asm volatile("cp.async.commit_group;")
#define CPWAIT1()  asm volatile("cp.async.wait_group 1;")
#define CPWAIT0()  asm volatile("cp.async.wait_group 0;")

// ---------------------------------------------------------------------------
// one-shot conversions
// ---------------------------------------------------------------------------
__global__ __launch_bounds__(256) void split_kernel(
    const float* __restrict__ src, unsigned* __restrict__ hi,
    unsigned* __restrict__ lo, int n2)
{
    int i = blockIdx.x * 256 + threadIdx.x;
    if (i < n2) {
        float2 v = reinterpret_cast<const float2*>(src)[i];
        unsigned h, l;
        split2(v.x, v.y, h, l);
        hi[i] = h;
        lo[i] = l;
    }
}

// W[k][n] -> Wt[n][k] as bf16 hi/lo (u32 = k-pair)
__global__ __launch_bounds__(256) void tsplit_kernel(
    const float* __restrict__ W, unsigned* __restrict__ Th, unsigned* __restrict__ Tl)
{
    __shared__ float t[64][65];
    const int k0 = blockIdx.y * 64, n0 = blockIdx.x * 64;
#pragma unroll
    for (int i = 0; i < 16; i++) {
        int idx = threadIdx.x + i * 256;
        int k = idx >> 6, n = idx & 63;
        t[k][n] = W[(size_t)(k0 + k) * DIM + n0 + n];
    }
    __syncthreads();
#pragma unroll
    for (int i = 0; i < 8; i++) {
        int idx = threadIdx.x + i * 256;
        int n = idx >> 5, kp = idx & 31;
        unsigned h, l;
        split2(t[2 * kp][n], t[2 * kp + 1][n], h, l);
        size_t o = (size_t)(n0 + n) * U32DIM + k0 / 2 + kp;
        Th[o] = h;
        Tl[o] = l;
    }
}

// ---------------------------------------------------------------------------
// GEMM (pre-split bf16, 3-stage cp.async, XOR-swizzled 32KB stages):
//   C[8192,1024] = A @ Wt^T + bias.  Block 128x128, k-chunk 32, 256 threads
//   (8 warps, warp tile 32x64), 2 CTAs/SM (192KB smem total).  bf16x3.
//   mode 0: Cf = fp32.  mode 1: split(val*scale) -> Ch/Cl.
// ---------------------------------------------------------------------------
#define OAH 0
#define OAL 2048
#define OBH 4096
#define OBL 6144
#define GSTG 8192     // u32 per stage (32KB)
#define GSMEM_BYTES (3 * GSTG * 4)   // 98304 per CTA

__device__ __forceinline__ uint32_t gsw(uint32_t row, uint32_t cj) {
    return (row * 16 + (cj ^ ((row >> 1) & 3)) * 4) * 4;   // byte offset
}

__global__ __launch_bounds__(256, 2) void gemm_bf16_kernel(
    const unsigned* __restrict__ Ahp, const unsigned* __restrict__ Alp,
    const unsigned* __restrict__ Bhp, const unsigned* __restrict__ Blp,
    const float* __restrict__ bias, float* __restrict__ Cf,
    unsigned* __restrict__ Ch, unsigned* __restrict__ Cl,
    float scale, int mode)
{
    extern __shared__ unsigned gsm[];
    const uint32_t sb = smem_u32(gsm);

    const int tid  = threadIdx.x;
    const int lane = tid & 31;
    const int warp = tid >> 5;    // 0..7
    const int grp  = lane >> 2;
    const int q4   = lane & 3;
    const int wm   = warp >> 1;   // 0..3 (32-row group)
    const int wn   = warp & 1;    // 0..1 (64-col group)
    const int m0 = blockIdx.y * 128;
    const int n0 = blockIdx.x * 128;

    const uint4* A4h = reinterpret_cast<const uint4*>(Ahp);
    const uint4* A4l = reinterpret_cast<const uint4*>(Alp);
    const uint4* B4h = reinterpret_cast<const uint4*>(Bhp);
    const uint4* B4l = reinterpret_cast<const uint4*>(Blp);

    float acc[2][4][2][4];   // [mi][tt][hf][4]
#pragma unroll
    for (int a = 0; a < 2; a++)
#pragma unroll
        for (int b = 0; b < 4; b++)
#pragma unroll
            for (int c = 0; c < 2; c++)
#pragma unroll
                for (int d = 0; d < 4; d++) acc[a][b][c][d] = 0.f;

    const int crow = tid >> 2;          // 0..63
    const int cj   = tid & 3;

    auto copy_chunk = [&](int chunk, int stage) {
        const uint32_t su = sb + stage * GSTG * 4;
        const uint32_t d0 = gsw(crow, cj);
        const uint32_t d1 = gsw(crow + 64, cj);
        const uint4* aTh = A4h + (size_t)(m0 + crow) * U4DIM + chunk * 4 + cj;
        const uint4* aTl = A4l + (size_t)(m0 + crow) * U4DIM + chunk * 4 + cj;
        const uint4* bTh = B4h + (size_t)(n0 + crow) * U4DIM + chunk * 4 + cj;
        const uint4* bTl = B4l + (size_t)(n0 + crow) * U4DIM + chunk * 4 + cj;
        CPA16(su + OAH * 4 + d0, aTh);
        CPA16(su + OAH * 4 + d1, aTh + (size_t)64 * U4DIM);
        CPA16(su + OAL * 4 + d0, aTl);
        CPA16(su + OAL * 4 + d1, aTl + (size_t)64 * U4DIM);
        CPA16(su + OBH * 4 + d0, bTh);
        CPA16(su + OBH * 4 + d1, bTh + (size_t)64 * U4DIM);
        CPA16(su + OBL * 4 + d0, bTl);
        CPA16(su + OBL * 4 + d1, bTl + (size_t)64 * U4DIM);
    };

    auto compute_chunk = [&](int stage) {
        const uint32_t su = sb + stage * GSTG * 4;
#pragma unroll
        for (int kk = 0; kk < 2; kk++) {
            unsigned bh[4][4], bl[4][4];
#pragma unroll
            for (int tt = 0; tt < 4; tt++) {
                uint32_t brow = wn * 64 + tt * 16 + ((lane >> 4) << 3) + (lane & 7);
                uint32_t bj = kk * 2 + ((lane >> 3) & 1);
                uint32_t boff = gsw(brow, bj);
                LDSM4(bh[tt][0], bh[tt][1], bh[tt][2], bh[tt][3], su + OBH * 4 + boff);
                LDSM4(bl[tt][0], bl[tt][1], bl[tt][2], bl[tt][3], su + OBL * 4 + boff);
            }
#pragma unroll
            for (int mi = 0; mi < 2; mi++) {
                unsigned ah[4], al[4];
                uint32_t arow = wm * 32 + mi * 16 + (lane & 15);
                uint32_t aj = kk * 2 + (lane >> 4);
                uint32_t aoff = gsw(arow, aj);
                LDSM4(ah[0], ah[1], ah[2], ah[3], su + OAH * 4 + aoff);
                LDSM4(al[0], al[1], al[2], al[3], su + OAL * 4 + aoff);
#pragma unroll
                for (int tt = 0; tt < 4; tt++) {
#pragma unroll
                    for (int hf = 0; hf < 2; hf++) {
                        float* c = acc[mi][tt][hf];
                        mma16816(c, ah, bh[tt][2 * hf], bh[tt][2 * hf + 1]);
                        mma16816(c, ah, bl[tt][2 * hf], bl[tt][2 * hf + 1]);
                        mma16816(c, al, bh[tt][2 * hf], bh[tt][2 * hf + 1]);
                    }
                }
            }
        }
    };

    // prologue: fill stages 0 and 1
    copy_chunk(0, 0); CPCOMMIT();
    copy_chunk(1, 1); CPCOMMIT();

    for (int c = 0; c < 32; c++) {
        if (c < 31) { CPWAIT1(); } else { CPWAIT0(); }
        __syncthreads();          // chunk c visible; all warps done with compute(c-1)
        if (c + 2 < 32) {         // refill stage (c+2)%3 = (c-1)%3
            copy_chunk(c + 2, (c + 2) % 3);
            CPCOMMIT();
        }
        compute_chunk(c % 3);
    }

    // ---- epilogue ----
#pragma unroll
    for (int mi = 0; mi < 2; mi++) {
        int row = m0 + wm * 32 + mi * 16 + grp;
#pragma unroll
        for (int tt = 0; tt < 4; tt++) {
#pragma unroll
            for (int hf = 0; hf < 2; hf++) {
                int col = n0 + wn * 64 + tt * 16 + hf * 8 + 2 * q4;
                float b0 = bias[col], b1 = bias[col + 1];
                const float* a = acc[mi][tt][hf];
                float v0 = a[0] + b0, v1 = a[1] + b1;
                float v2 = a[2] + b0, v3 = a[3] + b1;
                if (mode == 0) {
                    *reinterpret_cast<float2*>(Cf + (size_t)row * DIM + col) =
                        make_float2(v0, v1);
                    *reinterpret_cast<float2*>(Cf + (size_t)(row + 8) * DIM + col) =
                        make_float2(v2, v3);
                } else {
                    unsigned h, l;
                    split2(v0 * scale, v1 * scale, h, l);
                    size_t o0 = (size_t)row * U32DIM + col / 2;
                    Ch[o0] = h; Cl[o0] = l;
                    split2(v2 * scale, v3 * scale, h, l);
                    size_t o1 = (size_t)(row + 8) * U32DIM + col / 2;
                    Ch[o1] = h; Cl[o1] = l;
                }
            }
        }
    }
}

// ---------------------------------------------------------------------------
// Flash attention (exact round-6 winner): shift-free base-2 softmax,
// q-tile 128 x 256 threads; kv-tile 64, 2-stage cp.async ring.
// ---------------------------------------------------------------------------
#define AST 36
#define AQH 0
#define AQL 4608
#define AKH 9216
#define AKL 13824
#define AVH 18432
#define AVL 23040
#define KSTG 2304
#define ATTN_SMEM_BYTES (27648 * 4)   // 110592

__global__ __launch_bounds__(256) void attn_kernel(
    const unsigned* __restrict__ Qhp, const unsigned* __restrict__ Qlp,
    const unsigned* __restrict__ Khp, const unsigned* __restrict__ Klp,
    const unsigned* __restrict__ Vhp, const unsigned* __restrict__ Vlp,
    unsigned* __restrict__ Ohg, unsigned* __restrict__ Olg)
{
    extern __shared__ unsigned smemA[];
    const uint32_t sb = smem_u32(smemA);

    const int tid  = threadIdx.x;
    const int lane = tid & 31;
    const int warp = tid >> 5;
    const int grp  = lane >> 2;
    const int q4   = lane & 3;

    const int bh = blockIdx.y;
    const int b  = bh >> 4;
    const int h  = bh & 15;
    const int q0 = blockIdx.x * 128;

    const uint4* Q4h = reinterpret_cast<const uint4*>(Qhp);
    const uint4* Q4l = reinterpret_cast<const uint4*>(Qlp);
    const uint4* K4h = reinterpret_cast<const uint4*>(Khp);
    const uint4* K4l = reinterpret_cast<const uint4*>(Klp);
    const uint4* V4h = reinterpret_cast<const uint4*>(Vhp);
    const uint4* V4l = reinterpret_cast<const uint4*>(Vlp);

    const size_t qrow0 = (size_t)(b * NQ + q0);
    const size_t hoff = (size_t)h * 8;

    // ---- Q copy ----
    {
        const int row8 = tid >> 3, j = tid & 7;
#pragma unroll
        for (int i = 0; i < 8; i++) {
            int r = ((i & 3) << 5) + row8;     // 0..127
            const uint4* src = ((i < 4) ? Q4h : Q4l) + (qrow0 + r) * U4ROW + hoff + j;
            uint32_t off = ((i < 4) ? AQH : AQL) + r * AST + j * 4;
            CPA16(sb + off * 4, src);
        }
    }

    auto copy_kv = [&](int tile, int stage) {
        const size_t krow0 = (size_t)(b * NKV + tile * 64);
        const int row8 = tid >> 3, j = tid & 7;
#pragma unroll
        for (int i = 0; i < 8; i++) {
            int r = ((i & 1) << 5) + row8;     // 0..63
            const uint4* src;
            uint32_t off;
            switch (i >> 1) {
                case 0:  src = K4h + (krow0 + r) * U4ROW + hoff + j; off = AKH; break;
                case 1:  src = K4l + (krow0 + r) * U4ROW + hoff + j; off = AKL; break;
                case 2:  src = V4h + (krow0 + r) * U4ROW + hoff + j; off = AVH; break;
                default: src = V4l + (krow0 + r) * U4ROW + hoff + j; off = AVL; break;
            }
            CPA16(sb + (off + stage * KSTG + r * AST + j * 4) * 4, src);
        }
    };

    copy_kv(0, 0);
    CPCOMMIT();

    float l0 = 0.f, l1 = 0.f;
    float o[8][4];
#pragma unroll
    for (int i = 0; i < 8; i++)
#pragma unroll
        for (int j = 0; j < 4; j++) o[i][j] = 0.f;

    const int r0w = warp * 16;

    for (int t = 0; t < 16; t++) {
        if (t < 15) {
            copy_kv(t + 1, (t + 1) & 1);
            CPCOMMIT();
            CPWAIT1();
        } else {
            CPWAIT0();
        }
        __syncthreads();

        const uint32_t sKH = sb + (AKH + (t & 1) * KSTG) * 4;
        const uint32_t sKL = sb + (AKL + (t & 1) * KSTG) * 4;
        const uint32_t sVH = sb + (AVH + (t & 1) * KSTG) * 4;
        const uint32_t sVL = sb + (AVL + (t & 1) * KSTG) * 4;

        // ---- S = Q K^T (64 kv cols) ----
        float s[8][4];
#pragma unroll
        for (int i = 0; i < 8; i++)
#pragma unroll
            for (int j = 0; j < 4; j++) s[i][j] = 0.f;

#pragma unroll
        for (int dk = 0; dk < 4; dk++) {
            unsigned qh_[4], ql_[4];
            uint32_t arow = r0w + (lane & 15);
            uint32_t aj = 2 * dk + (lane >> 4);
            uint32_t aoff = (arow * AST + aj * 4) * 4;
            LDSM4(qh_[0], qh_[1], qh_[2], qh_[3], sb + aoff);
            LDSM4(ql_[0], ql_[1], ql_[2], ql_[3], sb + AQL * 4 + aoff);
#pragma unroll
            for (int tt = 0; tt < 4; tt++) {
                unsigned kh_[4], kl_[4];
                uint32_t brow = tt * 16 + ((lane >> 4) << 3) + (lane & 7);
                uint32_t bj = 2 * dk + ((lane >> 3) & 1);
                uint32_t boff = (brow * AST + bj * 4) * 4;
                LDSM4(kh_[0], kh_[1], kh_[2], kh_[3], sKH + boff);
                LDSM4(kl_[0], kl_[1], kl_[2], kl_[3], sKL + boff);
                mma16816(s[2 * tt],     qh_, kh_[0], kh_[1]);
                mma16816(s[2 * tt],     qh_, kl_[0], kl_[1]);
                mma16816(s[2 * tt],     ql_, kh_[0], kh_[1]);
                mma16816(s[2 * tt + 1], qh_, kh_[2], kh_[3]);
                mma16816(s[2 * tt + 1], qh_, kl_[2], kl_[3]);
                mma16816(s[2 * tt + 1], ql_, kh_[2], kh_[3]);
            }
        }

        // ---- P = 2^s, thread-local l accumulation ----
#pragma unroll
        for (int ni = 0; ni < 8; ni++) {
            s[ni][0] = ex2(s[ni][0]); l0 += s[ni][0];
            s[ni][1] = ex2(s[ni][1]); l0 += s[ni][1];
            s[ni][2] = ex2(s[ni][2]); l1 += s[ni][2];
            s[ni][3] = ex2(s[ni][3]); l1 += s[ni][3];
        }

        // ---- O += P @ V  (V via trans-LDSM) ----
#pragma unroll
        for (int st = 0; st < 4; st++) {
            unsigned ph[4], pl[4];
            split2(s[2 * st][0],     s[2 * st][1],     ph[0], pl[0]);
            split2(s[2 * st][2],     s[2 * st][3],     ph[1], pl[1]);
            split2(s[2 * st + 1][0], s[2 * st + 1][1], ph[2], pl[2]);
            split2(s[2 * st + 1][2], s[2 * st + 1][3], ph[3], pl[3]);
#pragma unroll
            for (int tt = 0; tt < 4; tt++) {
                unsigned vh_[4], vl_[4];
                uint32_t vrow = st * 16 + (((lane >> 3) & 1) << 3) + (lane & 7);
                uint32_t vj = 2 * tt + (lane >> 4);
                uint32_t voff = (vrow * AST + vj * 4) * 4;
                LDSM4T(vh_[0], vh_[1], vh_[2], vh_[3], sVH + voff);
                LDSM4T(vl_[0], vl_[1], vl_[2], vl_[3], sVL + voff);
                mma16816(o[2 * tt],     ph, vh_[0], vh_[1]);
                mma16816(o[2 * tt],     ph, vl_[0], vl_[1]);
                mma16816(o[2 * tt],     pl, vh_[0], vh_[1]);
                mma16816(o[2 * tt + 1], ph, vh_[2], vh_[3]);
                mma16816(o[2 * tt + 1], ph, vl_[2], vl_[3]);
                mma16816(o[2 * tt + 1], pl, vh_[2], vh_[3]);
            }
        }
        __syncthreads();
    }

    // ---- one-time l reduction + epilogue (pre-split O) ----
    l0 += __shfl_xor_sync(0xffffffffu, l0, 1);
    l0 += __shfl_xor_sync(0xffffffffu, l0, 2);
    l1 += __shfl_xor_sync(0xffffffffu, l1, 1);
    l1 += __shfl_xor_sync(0xffffffffu, l1, 2);
    float inv0 = 1.f / l0, inv1 = 1.f / l1;
    const int r0 = q0 + warp * 16 + grp;
#pragma unroll
    for (int ni = 0; ni < 8; ni++) {
        int c = ni * 8 + 2 * q4;
        unsigned hh, ll;
        split2(o[ni][0] * inv0, o[ni][1] * inv0, hh, ll);
        size_t o0 = (size_t)(b * NQ + r0) * U32DIM + h * 32 + c / 2;
        Ohg[o0] = hh; Olg[o0] = ll;
        split2(o[ni][2] * inv1, o[ni][3] * inv1, hh, ll);
        size_t o1 = (size_t)(b * NQ + r0 + 8) * U32DIM + h * 32 + c / 2;
        Ohg[o1] = hh; Olg[o1] = ll;
    }
}

// ---------------------------------------------------------------------------
// launch
// ---------------------------------------------------------------------------
extern "C" void kernel_launch(void* const* d_in, const int* in_sizes, int n_in,
                              void* d_out, int out_size)
{
    (void)in_sizes; (void)n_in; (void)out_size;
    const float* x   = (const float*)d_in[0];
    const float* ctx = (const float*)d_in[1];
    const float* Wq  = (const float*)d_in[2];
    const float* bq  = (const float*)d_in[3];
    const float* Wk  = (const float*)d_in[4];
    const float* bk  = (const float*)d_in[5];
    const float* Wv  = (const float*)d_in[6];
    const float* bv  = (const float*)d_in[7];
    const float* Wo  = (const float*)d_in[8];
    const float* bo  = (const float*)d_in[9];
    float* out = (float*)d_out;

    unsigned *xh, *xl, *ch, *cl;
    unsigned *wqh, *wql, *wkh, *wkl, *wvh, *wvl, *woh, *wol;
    unsigned *qh, *ql, *kh, *kl, *vh, *vl, *oh, *ol;
    cudaGetSymbolAddress((void**)&xh, g_xh);   cudaGetSymbolAddress((void**)&xl, g_xl);
    cudaGetSymbolAddress((void**)&ch, g_ch);   cudaGetSymbolAddress((void**)&cl, g_cl);
    cudaGetSymbolAddress((void**)&wqh, g_Wqh); cudaGetSymbolAddress((void**)&wql, g_Wql);
    cudaGetSymbolAddress((void**)&wkh, g_Wkh); cudaGetSymbolAddress((void**)&wkl, g_Wkl);
    cudaGetSymbolAddress((void**)&wvh, g_Wvh); cudaGetSymbolAddress((void**)&wvl, g_Wvl);
    cudaGetSymbolAddress((void**)&woh, g_Woh); cudaGetSymbolAddress((void**)&wol, g_Wol);
    cudaGetSymbolAddress((void**)&qh, g_Qh);   cudaGetSymbolAddress((void**)&ql, g_Ql);
    cudaGetSymbolAddress((void**)&kh, g_Kh);   cudaGetSymbolAddress((void**)&kl, g_Kl);
    cudaGetSymbolAddress((void**)&vh, g_Vh);   cudaGetSymbolAddress((void**)&vl, g_Vl);
    cudaGetSymbolAddress((void**)&oh, g_Oh);   cudaGetSymbolAddress((void**)&ol, g_Ol);

    cudaFuncSetAttribute(gemm_bf16_kernel,
                         cudaFuncAttributeMaxDynamicSharedMemorySize, GSMEM_BYTES);
    cudaFuncSetAttribute(attn_kernel,
                         cudaFuncAttributeMaxDynamicSharedMemorySize, ATTN_SMEM_BYTES);

    const int n2 = MROWS * U32DIM;
    const float QSCALE = 0.125f * 1.44269504088896340736f;
    dim3 gblk(256);
    dim3 ggrid(DIM / 128, MROWS / 128);   // (8, 64)

    split_kernel<<<n2 / 256, 256>>>(x,   xh, xl, n2);
    split_kernel<<<n2 / 256, 256>>>(ctx, ch, cl, n2);
    tsplit_kernel<<<dim3(16, 16), 256>>>(Wq, wqh, wql);
    tsplit_kernel<<<dim3(16, 16), 256>>>(Wk, wkh, wkl);
    tsplit_kernel<<<dim3(16, 16), 256>>>(Wv, wvh, wvl);
    gemm_bf16_kernel<<<ggrid, gblk, GSMEM_BYTES>>>(
        xh, xl, wqh, wql, bq, nullptr, qh, ql, QSCALE, 1);
    gemm_bf16_kernel<<<ggrid, gblk, GSMEM_BYTES>>>(
        ch, cl, wkh, wkl, bk, nullptr, kh, kl, 1.f, 1);
    gemm_bf16_kernel<<<ggrid, gblk, GSMEM_BYTES>>>(
        ch, cl, wvh, wvl, bv, nullptr, vh, vl, 1.f, 1);
    tsplit_kernel<<<dim3(16, 16), 256>>>(Wo, woh, wol);
    attn_kernel<<<dim3(NQ / 128, BATCH * NHEADS), 256, ATTN_SMEM_BYTES>>>(
        qh, ql, kh, kl, vh, vl, oh, ol);
    gemm_bf16_kernel<<<ggrid, gblk, GSMEM_BYTES>>>(
        oh, ol, woh, wol, bo, out, nullptr, nullptr, 1.f, 0);
}